// round 17
// baseline (speedup 1.0000x reference)
#include <cuda_runtime.h>
#include <cuda_bf16.h>
#include <cstdint>

// ============================================================================
// Problem constants
// ============================================================================
static constexpr int NROW = 6144;
static constexpr int DIM  = 768;
static constexpr int DIM_U4 = DIM / 8;   // 96 uint4 per row (bf16)
static constexpr float INV_T = 14.285714285714286f;   // 1/0.07

// GEMM tiling: CTA 128x128, 8 warps (2x4), warp tile 64x32, K staged at 64
static constexpr int NSTAGES = DIM / 64;    // 12
static constexpr int GRID    = NROW / 128;  // 48
static constexpr int NTILES  = GRID * (GRID + 1) / 2;  // 1176 upper-tri tiles

// Dynamic SMEM: 3 stages x 32KB (A 16K + B 16K), then acc arrays
static constexpr int STAGE_BYTES = 32768;
static constexpr int SMEM_ACC    = 3 * STAGE_BYTES;     // 98304
static constexpr int SMEM_TOTAL  = SMEM_ACC + 1536;     // row/col/pos acc

// ============================================================================
// Device scratch (no runtime allocation allowed)
// ============================================================================
__device__ uint4 g_fbf16[NROW * DIM_U4];   // normalized feats, bf16 row-major
__device__ float g_rowsum[NROW];           // sum_{j!=i} exp(sim_ij)
__device__ float g_possum[NROW];           // sum over positives exp(sim_ij)

// ============================================================================
// PTX helpers (base ISA only — compiles for .target sm_103)
// ============================================================================
__device__ __forceinline__ uint32_t smem_u32(const void* p) {
    uint32_t a;
    asm("{ .reg .u64 t; cvta.to.shared.u64 t, %1; cvt.u32.u64 %0, t; }"
        : "=r"(a) : "l"(p));
    return a;
}

__device__ __forceinline__ void ldsm_x4(uint32_t r[4], uint32_t addr) {
    asm volatile("ldmatrix.sync.aligned.m8n8.x4.shared.b16 {%0,%1,%2,%3}, [%4];"
                 : "=r"(r[0]), "=r"(r[1]), "=r"(r[2]), "=r"(r[3]) : "r"(addr));
}

__device__ __forceinline__ void mma16816(float c[4], const uint32_t a[4],
                                         const uint32_t b[2]) {
    asm volatile(
        "mma.sync.aligned.m16n8k16.row.col.f32.bf16.bf16.f32 "
        "{%0,%1,%2,%3}, {%4,%5,%6,%7}, {%8,%9}, {%0,%1,%2,%3};"
        : "+f"(c[0]), "+f"(c[1]), "+f"(c[2]), "+f"(c[3])
        : "r"(a[0]), "r"(a[1]), "r"(a[2]), "r"(a[3]), "r"(b[0]), "r"(b[1]));
}

#define CP_ASYNC16(dst, src) \
    asm volatile("cp.async.cg.shared.global [%0], [%1], 16;" \
                 :: "r"(dst), "l"(src) : "memory")
#define CP_ASYNC_COMMIT() \
    asm volatile("cp.async.commit_group;" ::: "memory")
#define CP_ASYNC_WAIT(n) \
    asm volatile("cp.async.wait_group %0;" :: "n"(n) : "memory")

// SW128-style swizzle on byte offsets within a 128B-row tile
__device__ __forceinline__ uint32_t swz(uint32_t off) {
    return off ^ ((off >> 3) & 0x70);
}

// exp(d / 0.07): 1 FMUL + 1 MUFU (hardware exp2), rel err ~1e-6
__device__ __forceinline__ float fast_exp_scaled(float d) {
    return __expf(d * INV_T);
}

// ============================================================================
// Kernels 0a/0b: zero the accumulators and output (also shifts the launch
// index so the ncu capture (absolute launch idx 3) lands on the GEMM).
// ============================================================================
__global__ void zero_a_kernel() {
    g_rowsum[blockIdx.x * 256 + threadIdx.x] = 0.f;
}
__global__ void zero_b_kernel(float* __restrict__ out) {
    int i = blockIdx.x * 256 + threadIdx.x;
    g_possum[i] = 0.f;
    if (i == 0) out[0] = 0.f;
}

// ============================================================================
// Kernel 1: L2-normalize rows -> bf16. One warp per TWO rows: 12 independent
// float4 loads in flight per lane (2x the MLP of one-row-per-warp), shuffle
// reductions, coalesced uint2 bf16 stores. No smem, no __syncthreads.
// ============================================================================
__global__ __launch_bounds__(256) void normalize_kernel(
        const float4* __restrict__ feats4) {
    const int warp = blockIdx.x * 8 + (threadIdx.x >> 5);
    const int lane = threadIdx.x & 31;
    const int r0 = warp * 2;

    const float4* s0 = feats4 + (size_t)r0 * (DIM / 4);        // 192 f4/row
    const float4* s1 = s0 + (DIM / 4);
    float4 v0[6], v1[6];
    #pragma unroll
    for (int i = 0; i < 6; ++i) {
        v0[i] = s0[lane + 32 * i];
        v1[i] = s1[lane + 32 * i];
    }
    float ss0 = 0.f, ss1 = 0.f;
    #pragma unroll
    for (int i = 0; i < 6; ++i) {
        ss0 = fmaf(v0[i].x, v0[i].x, ss0);
        ss0 = fmaf(v0[i].y, v0[i].y, ss0);
        ss0 = fmaf(v0[i].z, v0[i].z, ss0);
        ss0 = fmaf(v0[i].w, v0[i].w, ss0);
        ss1 = fmaf(v1[i].x, v1[i].x, ss1);
        ss1 = fmaf(v1[i].y, v1[i].y, ss1);
        ss1 = fmaf(v1[i].z, v1[i].z, ss1);
        ss1 = fmaf(v1[i].w, v1[i].w, ss1);
    }
    #pragma unroll
    for (int o = 16; o; o >>= 1) {
        ss0 += __shfl_xor_sync(0xFFFFFFFFu, ss0, o);
        ss1 += __shfl_xor_sync(0xFFFFFFFFu, ss1, o);
    }
    const float rn0 = 1.f / fmaxf(sqrtf(ss0), 1e-12f);
    const float rn1 = 1.f / fmaxf(sqrtf(ss1), 1e-12f);

    uint2* d0 = ((uint2*)g_fbf16) + (size_t)r0 * (DIM / 4);    // 8B = 4 bf16
    uint2* d1 = d0 + (DIM / 4);
    #pragma unroll
    for (int i = 0; i < 6; ++i) {
        __nv_bfloat162 a0 = __floats2bfloat162_rn(v0[i].x * rn0, v0[i].y * rn0);
        __nv_bfloat162 b0 = __floats2bfloat162_rn(v0[i].z * rn0, v0[i].w * rn0);
        __nv_bfloat162 a1 = __floats2bfloat162_rn(v1[i].x * rn1, v1[i].y * rn1);
        __nv_bfloat162 b1 = __floats2bfloat162_rn(v1[i].z * rn1, v1[i].w * rn1);
        uint2 p0, p1;
        p0.x = *(uint32_t*)&a0; p0.y = *(uint32_t*)&b0;
        p1.x = *(uint32_t*)&a1; p1.y = *(uint32_t*)&b1;
        d0[lane + 32 * i] = p0;
        d1[lane + 32 * i] = p1;
    }
}

// ============================================================================
// Kernel 2: 128x128 bf16 GEMM tile (mma.sync) + fused exp / diag mask /
// row+col sums / positive-pair sums. Upper-triangular tiles only; the
// symmetric mirror is supplied via column sums.
// ============================================================================
__global__ __launch_bounds__(256, 2) void gemm_lse_kernel() {
    // 1D -> upper-triangular (bm, bn) mapping
    int idx = blockIdx.x, bm = 0, rem = GRID;
    while (idx >= rem) { idx -= rem; --rem; ++bm; }
    const int bn = bm + idx;

    extern __shared__ __align__(1024) char smem[];
    const uint32_t sb = smem_u32(smem);
    const int tid  = threadIdx.x;
    const int lane = tid & 31;
    const int w    = tid >> 5;            // 8 warps
    const int wm   = (w >> 2) * 64;       // warp row offset within tile
    const int wn   = (w & 3) * 32;        // warp col offset within tile
    const int m0 = bm * 128, n0 = bn * 128;
    const bool diag = (bm == bn);
    const bool adj  = (bn == bm + 1);     // may hold straddling positive pairs

    float* rowacc = (float*)(smem + SMEM_ACC);
    float* colacc = rowacc + 128;
    float* posacc = colacc + 128;
    if (tid < 128) { rowacc[tid] = 0.f; colacc[tid] = 0.f; posacc[tid] = 0.f; }

    const uint4* __restrict__ gA = g_fbf16 + (size_t)m0 * DIM_U4;
    const uint4* __restrict__ gB = g_fbf16 + (size_t)n0 * DIM_U4;

    float acc[4][4][4];
    #pragma unroll
    for (int i = 0; i < 4; ++i)
        #pragma unroll
        for (int j = 0; j < 4; ++j)
            #pragma unroll
            for (int k = 0; k < 4; ++k) acc[i][j][k] = 0.f;

    // ---- stage loader: 16B cp.async per thread x 4 iters per operand ----
    auto load_stage = [&](int c, int s) {
        uint32_t aBase = sb + s * STAGE_BYTES;
        uint32_t bBase = aBase + 16384;
        #pragma unroll
        for (int i = 0; i < 4; ++i) {
            int id = tid + i * 256;       // 1024 chunks: 128 rows x 8
            int r = id >> 3, ch = id & 7;
            uint32_t off = swz((uint32_t)(r * 128 + ch * 16));
            CP_ASYNC16(aBase + off, &gA[r * DIM_U4 + c * 8 + ch]);
            CP_ASYNC16(bBase + off, &gB[r * DIM_U4 + c * 8 + ch]);
        }
        CP_ASYNC_COMMIT();
    };

    // ---- compute one K=64 stage: 4 k16-steps x (4x4) mma per warp ----
    const int arow  = wm + (lane & 15);
    const uint32_t acolp = (uint32_t)((lane >> 4) << 4);
    const int brow  = wn + ((lane >> 4) << 3) + (lane & 7);
    const uint32_t bcolp = (uint32_t)(((lane >> 3) & 1) << 4);

    auto compute_stage = [&](int s) {
        uint32_t aBase = sb + s * STAGE_BYTES;
        uint32_t bBase = aBase + 16384;
        #pragma unroll
        for (int ks = 0; ks < 4; ++ks) {
            uint32_t af[4][4];
            #pragma unroll
            for (int mt = 0; mt < 4; ++mt) {
                uint32_t off = swz((uint32_t)((arow + mt * 16) * 128) +
                                   (uint32_t)(ks * 32) + acolp);
                ldsm_x4(af[mt], aBase + off);
            }
            uint32_t bf[4][2];
            #pragma unroll
            for (int p = 0; p < 2; ++p) {
                uint32_t t4[4];
                uint32_t off = swz((uint32_t)((brow + p * 16) * 128) +
                                   (uint32_t)(ks * 32) + bcolp);
                ldsm_x4(t4, bBase + off);
                bf[2 * p][0]     = t4[0]; bf[2 * p][1]     = t4[1];
                bf[2 * p + 1][0] = t4[2]; bf[2 * p + 1][1] = t4[3];
            }
            #pragma unroll
            for (int mt = 0; mt < 4; ++mt)
                #pragma unroll
                for (int nt = 0; nt < 4; ++nt)
                    mma16816(acc[mt][nt], af[mt], bf[nt]);
        }
    };

    // ---- 3-stage software pipeline, one sync per K-stage ----
    load_stage(0, 0);
    load_stage(1, 1);
    #pragma unroll 1
    for (int c = 0; c < NSTAGES; ++c) {
        if (c < NSTAGES - 1) { CP_ASYNC_WAIT(1); } else { CP_ASYNC_WAIT(0); }
        __syncthreads();                   // load(c) visible; compute(c-1) done
        if (c + 2 < NSTAGES) load_stage(c + 2, (c + 2) % 3);
        compute_stage(c % 3);
    }

    // ---- epilogue: exp + diag mask; row / col / positive partials ----
    float rowp[4][2], colp[4][2], posp[4][2];
    #pragma unroll
    for (int i = 0; i < 4; ++i) {
        rowp[i][0] = rowp[i][1] = 0.f;
        colp[i][0] = colp[i][1] = 0.f;
        posp[i][0] = posp[i][1] = 0.f;
    }
    const int rl0 = wm + (lane >> 2);
    const int cl0 = wn + 2 * (lane & 3);
    #pragma unroll
    for (int mt = 0; mt < 4; ++mt) {
        int r0 = rl0 + mt * 16, r1 = r0 + 8;
        #pragma unroll
        for (int nt = 0; nt < 4; ++nt) {
            int c0 = cl0 + nt * 8, c1 = c0 + 1;
            float e00 = fast_exp_scaled(acc[mt][nt][0]);
            float e01 = fast_exp_scaled(acc[mt][nt][1]);
            float e10 = fast_exp_scaled(acc[mt][nt][2]);
            float e11 = fast_exp_scaled(acc[mt][nt][3]);
            if (diag) {
                if (r0 == c0) e00 = 0.f;
                if (r0 == c1) e01 = 0.f;
                if (r1 == c0) e10 = 0.f;
                if (r1 == c1) e11 = 0.f;
                // positives: same global group of 3 (self already zeroed)
                int gr0 = (m0 + r0) / 3, gr1 = (m0 + r1) / 3;
                int gc0 = (n0 + c0) / 3, gc1 = (n0 + c1) / 3;
                posp[mt][0] += (gr0 == gc0 ? e00 : 0.f) + (gr0 == gc1 ? e01 : 0.f);
                posp[mt][1] += (gr1 == gc0 ? e10 : 0.f) + (gr1 == gc1 ? e11 : 0.f);
            }
            if (adj && mt == 3 && nt == 0) {
                // straddling group across the 128-boundary (128 % 3 != 0):
                // only rows n0-2..n0-1 x cols n0..n0+1 can qualify (<=2 elems)
                int gr1g = m0 + r1;
                if (gr1g >= n0 - 2 && c0 <= 1) {
                    if ((gr1g / 3) == ((n0 + c0) / 3)) {
                        atomicAdd(&g_possum[gr1g], e10);
                        atomicAdd(&g_possum[n0 + c0], e10);
                    }
                    if ((gr1g / 3) == ((n0 + c1) / 3)) {
                        atomicAdd(&g_possum[gr1g], e11);
                        atomicAdd(&g_possum[n0 + c1], e11);
                    }
                }
            }
            rowp[mt][0] += e00 + e01;
            rowp[mt][1] += e10 + e11;
            colp[nt][0] += e00 + e10;
            colp[nt][1] += e01 + e11;
        }
    }
    // row reduce: lanes sharing (lane>>2) hold the same rows
    #pragma unroll
    for (int mt = 0; mt < 4; ++mt)
        #pragma unroll
        for (int h = 0; h < 2; ++h) {
            float v = rowp[mt][h];
            v += __shfl_xor_sync(0xFFFFFFFFu, v, 1);
            v += __shfl_xor_sync(0xFFFFFFFFu, v, 2);
            float q = posp[mt][h];
            q += __shfl_xor_sync(0xFFFFFFFFu, q, 1);
            q += __shfl_xor_sync(0xFFFFFFFFu, q, 2);
            if ((lane & 3) == 0) {
                int rr = wm + mt * 16 + (lane >> 2) + 8 * h;
                atomicAdd(&rowacc[rr], v);
                if (diag) atomicAdd(&posacc[rr], q);
            }
        }
    // col reduce: lanes sharing (lane&3) hold the same cols
    #pragma unroll
    for (int nt = 0; nt < 4; ++nt)
        #pragma unroll
        for (int j = 0; j < 2; ++j) {
            float v = colp[nt][j];
            v += __shfl_xor_sync(0xFFFFFFFFu, v, 4);
            v += __shfl_xor_sync(0xFFFFFFFFu, v, 8);
            v += __shfl_xor_sync(0xFFFFFFFFu, v, 16);
            if (lane < 4)
                atomicAdd(&colacc[wn + nt * 8 + 2 * lane + j], v);
        }
    __syncthreads();
    if (tid < 128) {
        atomicAdd(&g_rowsum[m0 + tid], rowacc[tid]);
        if (!diag) atomicAdd(&g_rowsum[n0 + tid], colacc[tid]);
        if (diag)  atomicAdd(&g_possum[m0 + tid], posacc[tid]);
    }
}

// ============================================================================
// Kernel 3: parallel final reduction -> loss scalar
// ============================================================================
__global__ void finalize_kernel(float* __restrict__ out) {
    int i = blockIdx.x * 256 + threadIdx.x;   // 24 x 256 = 6144 threads
    float v = logf(g_rowsum[i] / g_possum[i]);
    #pragma unroll
    for (int o = 16; o; o >>= 1) v += __shfl_xor_sync(0xFFFFFFFFu, v, o);
    __shared__ float sr[8];
    int lane = threadIdx.x & 31, wrp = threadIdx.x >> 5;
    if (lane == 0) sr[wrp] = v;
    __syncthreads();
    if (threadIdx.x < 8) {
        float s = sr[threadIdx.x];
        #pragma unroll
        for (int o = 4; o; o >>= 1) s += __shfl_xor_sync(0xFFu, s, o);
        if (threadIdx.x == 0) atomicAdd(out, s * (1.0f / (float)NROW));
    }
}

// ============================================================================
// Launch
// ============================================================================
extern "C" void kernel_launch(void* const* d_in, const int* in_sizes, int n_in,
                              void* d_out, int out_size) {
    const float4* feats4 = (const float4*)d_in[0];
    float* out = (float*)d_out;
    (void)in_sizes; (void)n_in; (void)out_size;

    zero_a_kernel<<<NROW / 256, 256>>>();
    zero_b_kernel<<<NROW / 256, 256>>>(out);
    normalize_kernel<<<NROW / 16, 256>>>(feats4);

    cudaFuncSetAttribute(gemm_lse_kernel,
                         cudaFuncAttributeMaxDynamicSharedMemorySize, SMEM_TOTAL);
    gemm_lse_kernel<<<NTILES, 256, SMEM_TOTAL>>>();

    finalize_kernel<<<NROW / 256, 256>>>(out);
}